// round 5
// baseline (speedup 1.0000x reference)
#include <cuda_runtime.h>
#include <cuda_bf16.h>
#include <cstdint>

typedef unsigned long long ull;

#define HIDDEN 2048
#define K3     6144          // 3 * HIDDEN (bf16x3 split along K)
#define HEADS  16
#define HD     128
#define NB     2
#define SEQ    2048
#define MTOT   4096
#define BK     64
#define NSTAGE (K3/BK)       // 96

// ---------------- scratch ----------------------------------------------------
__device__ __align__(128) __nv_bfloat16 g_Xp[(size_t)MTOT*K3];
__device__ __align__(128) __nv_bfloat16 g_Wp[4][(size_t)HIDDEN*K3];
__device__ __align__(128) __nv_bfloat16 g_Cp[(size_t)MTOT*K3];   // attn out, split
__device__ float g_q[(size_t)NB*HEADS*SEQ*HD];     // [B,H,S,Hd] rope+scale applied
__device__ float g_k[(size_t)NB*HEADS*SEQ*HD];
__device__ float g_v[(size_t)NB*HEADS*SEQ*HD];
__device__ float g_cos[SEQ*64];
__device__ float g_sin[SEQ*64];

// ---------------- helpers ----------------------------------------------------
__device__ __forceinline__ ull pack2(float lo, float hi) {
    ull d;
    asm("mov.b64 %0, {%1, %2};" : "=l"(d)
        : "r"(__float_as_uint(lo)), "r"(__float_as_uint(hi)));
    return d;
}
__device__ __forceinline__ void unpack2(ull d, float& lo, float& hi) {
    unsigned a, b;
    asm("mov.b64 {%0, %1}, %2;" : "=r"(a), "=r"(b) : "l"(d));
    lo = __uint_as_float(a); hi = __uint_as_float(b);
}
__device__ __forceinline__ void fma2(ull& c, ull a, ull b) {
    asm("fma.rn.f32x2 %0, %1, %2, %3;" : "=l"(c) : "l"(a), "l"(b), "l"(c));
}
__device__ __forceinline__ void mul2(ull& c, ull a, ull b) {
    asm("mul.rn.f32x2 %0, %1, %2;" : "=l"(c) : "l"(a), "l"(b), "l"(c));
}
__device__ __forceinline__ void mma16816(float* c, const uint32_t* a, const uint32_t* b) {
    asm volatile(
        "mma.sync.aligned.m16n8k16.row.col.f32.bf16.bf16.f32 "
        "{%0,%1,%2,%3}, {%4,%5,%6,%7}, {%8,%9}, {%0,%1,%2,%3};"
        : "+f"(c[0]), "+f"(c[1]), "+f"(c[2]), "+f"(c[3])
        : "r"(a[0]), "r"(a[1]), "r"(a[2]), "r"(a[3]), "r"(b[0]), "r"(b[1]));
}
__device__ __forceinline__ void cp_async16(uint32_t saddr, const void* gaddr) {
    asm volatile("cp.async.ca.shared.global [%0], [%1], 16;"
                 :: "r"(saddr), "l"(gaddr));
}
#define CP_COMMIT() asm volatile("cp.async.commit_group;" ::: "memory")
#define CP_WAIT(n)  asm volatile("cp.async.wait_group %0;" :: "n"(n) : "memory")
#define LDMX4(d0,d1,d2,d3,addr) \
    asm volatile("ldmatrix.sync.aligned.m8n8.x4.shared.b16 {%0,%1,%2,%3}, [%4];" \
                 : "=r"(d0), "=r"(d1), "=r"(d2), "=r"(d3) : "r"(addr))
__device__ __forceinline__ uint32_t smem_u32(const void* p) {
    uint32_t a;
    asm("{ .reg .u64 t; cvta.to.shared.u64 t, %1; cvt.u32.u64 %0, t; }" : "=r"(a) : "l"(p));
    return a;
}

// ---------------- RoPE table -------------------------------------------------
__global__ void rope_table_kernel() {
    int idx = blockIdx.x * blockDim.x + threadIdx.x;
    if (idx >= SEQ * 64) return;
    int s = idx >> 6, i = idx & 63;
    double invf = pow(10000.0, -(double)i / 64.0);
    double ang = (double)s * invf;
    g_cos[idx] = (float)cos(ang);
    g_sin[idx] = (float)sin(ang);
}

// ---------------- bf16x3 split conversion (float4 vectorized) ----------------
// wmode=0 (A): [k]=hi, [2048+k]=hi, [4096+k]=lo
// wmode=1 (W): [k]=hi, [2048+k]=lo, [4096+k]=hi
__global__ void convert_split(const float* __restrict__ src,
                              __nv_bfloat16* __restrict__ dst,
                              int rows, int wmode) {
    long idx = (long)blockIdx.x * blockDim.x + threadIdx.x;   // one float4
    if (idx >= (long)rows * (HIDDEN / 4)) return;
    long r = idx >> 9;               // / 512
    int k = (int)(idx & 511) << 2;
    float4 x = ((const float4*)src)[idx];
    __nv_bfloat16 h0 = __float2bfloat16(x.x), h1 = __float2bfloat16(x.y);
    __nv_bfloat16 h2 = __float2bfloat16(x.z), h3 = __float2bfloat16(x.w);
    __nv_bfloat16 l0 = __float2bfloat16(x.x - __bfloat162float(h0));
    __nv_bfloat16 l1 = __float2bfloat16(x.y - __bfloat162float(h1));
    __nv_bfloat16 l2 = __float2bfloat16(x.z - __bfloat162float(h2));
    __nv_bfloat16 l3 = __float2bfloat16(x.w - __bfloat162float(h3));
    __nv_bfloat16 hv[4] = {h0, h1, h2, h3};
    __nv_bfloat16 lv[4] = {l0, l1, l2, l3};
    __nv_bfloat16* d = dst + r * K3;
    uint2 hp = *(uint2*)hv, lp = *(uint2*)lv;
    *(uint2*)&d[k] = hp;
    *(uint2*)&d[HIDDEN + k]     = wmode ? lp : hp;
    *(uint2*)&d[2 * HIDDEN + k] = wmode ? hp : lp;
}

// ---------------- mma.sync GEMM: D[M,N] = A'[M,K3] * W'[N,K3]^T ---------------
// 128x128 tile, 256 threads (2x4 warps), BK=64, cp.async double buffer, ldmatrix.
#define TILE_STRIDE 144                   // 128B data + 16B pad per 64-bf16 row
#define ST          (128*TILE_STRIDE)     // 18432 per tile buffer
#define G_SMEM_BYTES (4*ST)               // 73728; epilogue Osm (67584) aliases

__global__ __launch_bounds__(256, 2)
void gemm_mma(const __nv_bfloat16* __restrict__ A,
              const __nv_bfloat16* __restrict__ Wq,
              const __nv_bfloat16* __restrict__ Wk,
              const __nv_bfloat16* __restrict__ Wv,
              float* __restrict__ Dq, float* __restrict__ Dk, float* __restrict__ Dv,
              int fused)
{
    extern __shared__ char smem[];
    uint32_t sb = smem_u32(smem);
    int tid = threadIdx.x;
    int wid = tid >> 5, lane = tid & 31;
    int warpm = wid >> 2, warpn = wid & 3;
    int lrw = lane >> 2, lk = lane & 3;     // c-fragment coords

    const __nv_bfloat16* W; float* D; int n0, mode;
    if (fused) {
        int which = blockIdx.x >> 4;
        n0 = (blockIdx.x & 15) * 128;
        W = (which == 0) ? Wq : (which == 1) ? Wk : Wv;
        D = (which == 0) ? Dq : (which == 1) ? Dk : Dv;
        mode = which;
    } else {
        n0 = blockIdx.x * 128; W = Wq; D = Dq; mode = 3;
    }
    int m0 = blockIdx.y * 128;

    const char* Ab = (const char*)(A + (size_t)m0 * K3);
    const char* Bb = (const char*)(W + (size_t)n0 * K3);

    float acc[4][4][4];
    #pragma unroll
    for (int i = 0; i < 4; i++)
        #pragma unroll
        for (int j = 0; j < 4; j++)
            #pragma unroll
            for (int r = 0; r < 4; r++) acc[i][j][r] = 0.f;

    int ld_r = tid >> 1, ld_c = (tid & 1) * 64;
    auto issue_stage = [&](int kelem, int buf) {
        uint32_t sA = sb + buf * ST + ld_r * TILE_STRIDE + ld_c;
        uint32_t sB = sA + 2 * ST;
        const char* gA = Ab + (size_t)kelem * 2 + (size_t)ld_r * (K3 * 2) + ld_c;
        const char* gB = Bb + (size_t)kelem * 2 + (size_t)ld_r * (K3 * 2) + ld_c;
        #pragma unroll
        for (int j = 0; j < 4; j++) {
            cp_async16(sA + j * 16, gA + j * 16);
            cp_async16(sB + j * 16, gB + j * 16);
        }
        CP_COMMIT();
    };

    // ldmatrix lane address offsets
    uint32_t aOff = (uint32_t)((warpm * 64 + (lane & 15)) * TILE_STRIDE + ((lane >> 4) << 4));
    uint32_t bOff = (uint32_t)((warpn * 32 + (lane & 7) + ((lane >> 4) << 3)) * TILE_STRIDE
                               + (((lane >> 3) & 1) << 4));

    issue_stage(0, 0);

    for (int st = 0; st < NSTAGE; st++) {
        if (st + 1 < NSTAGE) { issue_stage((st + 1) * BK, (st + 1) & 1); CP_WAIT(1); }
        else                 { CP_WAIT(0); }
        __syncthreads();

        uint32_t aB = sb + (st & 1) * ST + aOff;
        uint32_t bB = sb + 2 * ST + (st & 1) * ST + bOff;

        #pragma unroll
        for (int s = 0; s < 4; s++) {               // four k16 steps per BK=64
            uint32_t af[4][4], bf[4][2];
            #pragma unroll
            for (int i = 0; i < 4; i++)
                LDMX4(af[i][0], af[i][1], af[i][2], af[i][3],
                      aB + i * 16 * TILE_STRIDE + s * 32);
            #pragma unroll
            for (int p = 0; p < 2; p++) {
                uint32_t r0, r1, r2, r3;
                LDMX4(r0, r1, r2, r3, bB + p * 16 * TILE_STRIDE + s * 32);
                bf[2 * p][0] = r0; bf[2 * p][1] = r1;
                bf[2 * p + 1][0] = r2; bf[2 * p + 1][1] = r3;
            }
            #pragma unroll
            for (int i = 0; i < 4; i++)
                #pragma unroll
                for (int j = 0; j < 4; j++)
                    mma16816(acc[i][j], af[i], bf[j]);
        }
        __syncthreads();
    }

    // ---- epilogue: regs -> Osm, then fused RoPE/scale writes ----
    float* Osm = (float*)smem;
    #pragma unroll
    for (int i = 0; i < 4; i++) {
        int r0 = warpm * 64 + i * 16 + lrw;
        #pragma unroll
        for (int j = 0; j < 4; j++) {
            int c0 = warpn * 32 + j * 8 + lk * 2;
            Osm[r0 * 132 + c0]           = acc[i][j][0];
            Osm[r0 * 132 + c0 + 1]       = acc[i][j][1];
            Osm[(r0 + 8) * 132 + c0]     = acc[i][j][2];
            Osm[(r0 + 8) * 132 + c0 + 1] = acc[i][j][3];
        }
    }
    __syncthreads();

    if (mode == 3) {
        #pragma unroll
        for (int it = 0; it < 16; it++) {
            int f = it * 256 + tid;
            int r = f >> 5, c4 = (f & 31) << 2;
            float4 v = *(float4*)&Osm[r * 132 + c4];
            *(float4*)&D[(size_t)(m0 + r) * HIDDEN + n0 + c4] = v;
        }
    } else {
        int h = (n0 >> 7) & 15;
        const float scale = (mode == 0) ? 0.08838834764831845f : 1.0f;
        bool rope = (mode <= 1);
        #pragma unroll
        for (int it = 0; it < 32; it++) {
            int f = it * 256 + tid;
            int r = f >> 6, i = f & 63;
            int m = m0 + r;
            int b = m >> 11, s = m & (SEQ - 1);
            float x1 = Osm[r * 132 + i], x2 = Osm[r * 132 + i + 64];
            float o1, o2;
            if (rope) {
                float c = g_cos[s * 64 + i], sn = g_sin[s * 64 + i];
                o1 = (x1 * c - x2 * sn) * scale;
                o2 = (x2 * c + x1 * sn) * scale;
            } else { o1 = x1; o2 = x2; }
            size_t o = ((size_t)(b * HEADS + h) * SEQ + s) * HD + i;
            D[o] = o1; D[o + 64] = o2;
        }
    }
}

// ---------------- Flash-style causal attention -------------------------------
// f32x2 FFMA math; cp.async double-buffered KV; warp-local shfl softmax.
#define QPAD 132
#define SPAD 68
#define QS_F   (64*QPAD)            // 8448
#define KS_F   (64*QPAD)            // 8448 per buffer
#define VS_F   (64*HD)              // 8192 per buffer
#define OFF_K  QS_F
#define OFF_V  (QS_F + 2*KS_F)
#define OFF_S  (OFF_V + 2*VS_F)
#define OFF_M  (OFF_S + 64*SPAD)
#define OFF_L  (OFF_M + 64)
#define ATTN_SMEM_FLOATS (OFF_L + 64)
#define ATTN_SMEM_BYTES  (ATTN_SMEM_FLOATS * 4)
#define NEGINF __int_as_float(0xff800000)

__global__ __launch_bounds__(256)
void attn_kernel()
{
    extern __shared__ float sm[];
    float* Qs   = sm;
    float* mrow = sm + OFF_M;
    float* lrow = sm + OFF_L;
    float* Ss   = sm + OFF_S;
    uint32_t sb = smem_u32(sm);

    int tid = threadIdx.x;
    int tc = tid & 15, tr = tid >> 4;
    int qt = gridDim.x - 1 - blockIdx.x;
    int bh = blockIdx.y;
    long qbase = ((long)bh * SEQ + (long)qt * 64) * HD;

    // load Q tile (scale already fused in GEMM epilogue)
    #pragma unroll
    for (int it = 0; it < 8; it++) {
        int f = it * 256 + tid;
        int r = f >> 5, c4 = (f & 31) << 2;
        *(float4*)&Qs[r * QPAD + c4] = *(const float4*)&g_q[qbase + (long)r * HD + c4];
    }
    if (tid < 64) { mrow[tid] = NEGINF; lrow[tid] = 0.f; }

    // cp.async KV stage loader: 4 threads/row, 8 16B chunks each
    int kv_r = tid >> 2;
    int kv_c = (tid & 3) * 16;          // byte offset of first chunk (x4 stride 64B)
    auto issue_kv = [&](int kt, int buf) {
        long kvbase = ((long)bh * SEQ + (long)kt * 64) * HD;
        const char* gK = (const char*)(g_k + kvbase + kv_r * HD) + kv_c;
        const char* gV = (const char*)(g_v + kvbase + kv_r * HD) + kv_c;
        uint32_t sK = sb + (OFF_K + buf * KS_F) * 4 + kv_r * (QPAD * 4) + kv_c;
        uint32_t sV = sb + (OFF_V + buf * VS_F) * 4 + kv_r * (HD * 4) + kv_c;
        #pragma unroll
        for (int j = 0; j < 8; j++) {
            cp_async16(sK + j * 64, gK + j * 64);
            cp_async16(sV + j * 64, gV + j * 64);
        }
        CP_COMMIT();
    };

    ull accO[4][8];
    #pragma unroll
    for (int i = 0; i < 4; i++)
        #pragma unroll
        for (int u = 0; u < 8; u++) accO[i][u] = 0ULL;

    issue_kv(0, 0);

    for (int kt = 0; kt <= qt; kt++) {
        if (kt + 1 <= qt) { issue_kv(kt + 1, (kt + 1) & 1); CP_WAIT(1); }
        else              { CP_WAIT(0); }
        __syncthreads();

        const float* KsB = sm + OFF_K + (kt & 1) * KS_F;
        const float* VsB = sm + OFF_V + (kt & 1) * VS_F;

        // ---- scores ----
        ull sacc[4][4];
        #pragma unroll
        for (int i = 0; i < 4; i++)
            #pragma unroll
            for (int j = 0; j < 4; j++) sacc[i][j] = 0ULL;

        #pragma unroll 8
        for (int k = 0; k < HD; k += 2) {
            ull q2[4], k2[4];
            #pragma unroll
            for (int i = 0; i < 4; i++)
                q2[i] = *(const ull*)&Qs[(tr * 4 + i) * QPAD + k];
            #pragma unroll
            for (int j = 0; j < 4; j++)
                k2[j] = *(const ull*)&KsB[(tc + 16 * j) * QPAD + k];
            #pragma unroll
            for (int i = 0; i < 4; i++)
                #pragma unroll
                for (int j = 0; j < 4; j++)
                    fma2(sacc[i][j], q2[i], k2[j]);
        }

        // ---- warp-local online softmax (row group = 16 lanes, same tr) ----
        bool diag = (kt == qt);
        float co[4];
        #pragma unroll
        for (int i = 0; i < 4; i++) {
            int r = tr * 4 + i;
            float pv[4], m = NEGINF;
            #pragma unroll
            for (int j = 0; j < 4; j++) {
                int c = tc + 16 * j;
                float lo, hi; unpack2(sacc[i][j], lo, hi);
                float v = lo + hi;
                if (diag && c > r) v = NEGINF;
                pv[j] = v;
                m = fmaxf(m, v);
            }
            #pragma unroll
            for (int o = 8; o; o >>= 1) m = fmaxf(m, __shfl_xor_sync(0xffffffffu, m, o));
            float mo = mrow[r];
            float mx = fmaxf(m, mo);
            co[i] = __expf(mo - mx);
            float sum = 0.f;
            #pragma unroll
            for (int j = 0; j < 4; j++) {
                float p = __expf(pv[j] - mx);
                Ss[r * SPAD + tc + 16 * j] = p;
                sum += p;
            }
            #pragma unroll
            for (int o = 8; o; o >>= 1) sum += __shfl_xor_sync(0xffffffffu, sum, o);
            if (tc == 0) { mrow[r] = mx; lrow[r] = lrow[r] * co[i] + sum; }
        }
        __syncwarp();

        // ---- rescale + P@V ----
        #pragma unroll
        for (int i = 0; i < 4; i++) {
            ull c2 = pack2(co[i], co[i]);
            #pragma unroll
            for (int u = 0; u < 8; u++) mul2(accO[i][u], accO[i][u], c2);
        }
        #pragma unroll 4
        for (int kk = 0; kk < 64; kk += 2) {
            ull p2[4];
            #pragma unroll
            for (int i = 0; i < 4; i++)
                p2[i] = *(const ull*)&Ss[(tr * 4 + i) * SPAD + kk];
            #pragma unroll
            for (int u = 0; u < 8; u++) {
                int c = tc + 16 * u;
                ull v2 = pack2(VsB[kk * HD + c], VsB[(kk + 1) * HD + c]);
                #pragma unroll
                for (int i = 0; i < 4; i++)
                    fma2(accO[i][u], p2[i], v2);
            }
        }
        __syncthreads();
    }

    // ---- epilogue: normalize + fused bf16x3 split write into g_Cp ----
    __syncwarp();
    int bb = bh >> 4, h = bh & 15;
    #pragma unroll
    for (int i = 0; i < 4; i++) {
        int r = tr * 4 + i;
        float invl = 1.0f / lrow[r];
        size_t row = (size_t)bb * SEQ + (size_t)qt * 64 + r;
        __nv_bfloat16* d = g_Cp + row * K3;
        #pragma unroll
        for (int u = 0; u < 8; u++) {
            float lo, hi; unpack2(accO[i][u], lo, hi);
            float val = (lo + hi) * invl;
            int k = h * HD + tc + 16 * u;
            __nv_bfloat16 hb = __float2bfloat16(val);
            __nv_bfloat16 lb = __float2bfloat16(val - __bfloat162float(hb));
            d[k] = hb;                 // A-operand layout: [hi|hi|lo]
            d[HIDDEN + k] = hb;
            d[2 * HIDDEN + k] = lb;
        }
    }
}

// ---------------- launcher ----------------------------------------------------
extern "C" void kernel_launch(void* const* d_in, const int* in_sizes, int n_in,
                              void* d_out, int out_size)
{
    (void)in_sizes; (void)n_in; (void)out_size;
    const float* X  = (const float*)d_in[0];
    const float* wq = (const float*)d_in[1];
    const float* wk = (const float*)d_in[2];
    const float* wv = (const float*)d_in[3];
    const float* wo = (const float*)d_in[4];
    float* out = (float*)d_out;

    __nv_bfloat16 *xp, *wp, *cp;
    float *qp, *kp, *vp;
    cudaGetSymbolAddress((void**)&xp, g_Xp);
    cudaGetSymbolAddress((void**)&wp, g_Wp);
    cudaGetSymbolAddress((void**)&cp, g_Cp);
    cudaGetSymbolAddress((void**)&qp, g_q);
    cudaGetSymbolAddress((void**)&kp, g_k);
    cudaGetSymbolAddress((void**)&vp, g_v);
    __nv_bfloat16* wps[4];
    for (int i = 0; i < 4; i++) wps[i] = wp + (size_t)i * HIDDEN * K3;

    cudaFuncSetAttribute(gemm_mma, cudaFuncAttributeMaxDynamicSharedMemorySize, G_SMEM_BYTES);
    cudaFuncSetAttribute(attn_kernel, cudaFuncAttributeMaxDynamicSharedMemorySize, ATTN_SMEM_BYTES);

    rope_table_kernel<<<(SEQ * 64 + 255) / 256, 256>>>();

    convert_split<<<(MTOT * HIDDEN / 4 + 255) / 256, 256>>>(X,  xp,     MTOT,   0);
    convert_split<<<(HIDDEN * HIDDEN / 4 + 255) / 256, 256>>>(wq, wps[0], HIDDEN, 1);
    convert_split<<<(HIDDEN * HIDDEN / 4 + 255) / 256, 256>>>(wk, wps[1], HIDDEN, 1);
    convert_split<<<(HIDDEN * HIDDEN / 4 + 255) / 256, 256>>>(wv, wps[2], HIDDEN, 1);
    convert_split<<<(HIDDEN * HIDDEN / 4 + 255) / 256, 256>>>(wo, wps[3], HIDDEN, 1);

    // fused QKV projections + RoPE/scale epilogue
    gemm_mma<<<dim3(48, 32), 256, G_SMEM_BYTES>>>(xp, wps[0], wps[1], wps[2],
                                                  qp, kp, vp, 1);

    // attention (writes bf16x3-split ctx directly)
    attn_kernel<<<dim3(SEQ / 64, NB * HEADS), 256, ATTN_SMEM_BYTES>>>();

    // output projection -> d_out
    gemm_mma<<<dim3(16, 32), 256, G_SMEM_BYTES>>>(cp, wps[3], wps[3], wps[3],
                                                  out, out, out, 0);
}

// round 6
// speedup vs baseline: 1.2428x; 1.2428x over previous
#include <cuda_runtime.h>
#include <cuda_bf16.h>
#include <cstdint>

#define HIDDEN 2048
#define K3     6144
#define HEADS  16
#define HD     128
#define NB     2
#define SEQ    2048
#define MTOT   4096
#define BK     64
#define NSTAGE (K3/BK)

__device__ __align__(128) __nv_bfloat16 g_Xp[(size_t)MTOT*K3];
__device__ __align__(128) __nv_bfloat16 g_Wp[4][(size_t)HIDDEN*K3];
__device__ __align__(128) __nv_bfloat16 g_Cp[(size_t)MTOT*K3];
__device__ __align__(128) __nv_bfloat16 g_qp[(size_t)NB*HEADS*SEQ*256];  // [bh][s][hi128|lo128]
__device__ __align__(128) __nv_bfloat16 g_kp[(size_t)NB*HEADS*SEQ*256];
__device__ __align__(128) __nv_bfloat16 g_vh[(size_t)NB*HEADS*HD*SEQ];   // [bh][d][s]
__device__ __align__(128) __nv_bfloat16 g_vl[(size_t)NB*HEADS*HD*SEQ];
__device__ float g_cos[SEQ*64];
__device__ float g_sin[SEQ*64];

__device__ __forceinline__ void mma16816(float* c, const uint32_t* a, const uint32_t* b) {
    asm volatile(
        "mma.sync.aligned.m16n8k16.row.col.f32.bf16.bf16.f32 "
        "{%0,%1,%2,%3}, {%4,%5,%6,%7}, {%8,%9}, {%0,%1,%2,%3};"
        : "+f"(c[0]), "+f"(c[1]), "+f"(c[2]), "+f"(c[3])
        : "r"(a[0]), "r"(a[1]), "r"(a[2]), "r"(a[3]), "r"(b[0]), "r"(b[1]));
}
__device__ __forceinline__ void cp_async16(uint32_t saddr, const void* gaddr) {
    asm volatile("cp.async.ca.shared.global [%0], [%1], 16;" :: "r"(saddr), "l"(gaddr));
}
#define CP_COMMIT() asm volatile("cp.async.commit_group;" ::: "memory")
#define CP_WAIT(n)  asm volatile("cp.async.wait_group %0;" :: "n"(n) : "memory")
#define LDMX4(d0,d1,d2,d3,addr) \
    asm volatile("ldmatrix.sync.aligned.m8n8.x4.shared.b16 {%0,%1,%2,%3}, [%4];" \
                 : "=r"(d0), "=r"(d1), "=r"(d2), "=r"(d3) : "r"(addr))
#define PACK_BF2(dst, flo, fhi) \
    asm("cvt.rn.bf16x2.f32 %0, %1, %2;" : "=r"(dst) : "f"(fhi), "f"(flo))
__device__ __forceinline__ uint32_t smem_u32(const void* p) {
    uint32_t a;
    asm("{ .reg .u64 t; cvta.to.shared.u64 t, %1; cvt.u32.u64 %0, t; }" : "=r"(a) : "l"(p));
    return a;
}

__global__ void rope_table_kernel() {
    int idx = blockIdx.x * blockDim.x + threadIdx.x;
    if (idx >= SEQ * 64) return;
    int s = idx >> 6, i = idx & 63;
    double invf = pow(10000.0, -(double)i / 64.0);
    double ang = (double)s * invf;
    g_cos[idx] = (float)cos(ang);
    g_sin[idx] = (float)sin(ang);
}

__global__ void convert_split(const float* __restrict__ src,
                              __nv_bfloat16* __restrict__ dst, int rows, int wmode) {
    long idx = (long)blockIdx.x * blockDim.x + threadIdx.x;
    if (idx >= (long)rows * (HIDDEN / 4)) return;
    long r = idx >> 9;
    int k = (int)(idx & 511) << 2;
    float4 x = ((const float4*)src)[idx];
    __nv_bfloat16 hv[4] = {__float2bfloat16(x.x), __float2bfloat16(x.y),
                           __float2bfloat16(x.z), __float2bfloat16(x.w)};
    __nv_bfloat16 lv[4] = {__float2bfloat16(x.x - __bfloat162float(hv[0])),
                           __float2bfloat16(x.y - __bfloat162float(hv[1])),
                           __float2bfloat16(x.z - __bfloat162float(hv[2])),
                           __float2bfloat16(x.w - __bfloat162float(hv[3]))};
    __nv_bfloat16* d = dst + r * K3;
    uint2 hp = *(uint2*)hv, lp = *(uint2*)lv;
    *(uint2*)&d[k] = hp;
    *(uint2*)&d[HIDDEN + k]     = wmode ? lp : hp;
    *(uint2*)&d[2 * HIDDEN + k] = wmode ? hp : lp;
}

// ------------- GEMM (R4 core, new epilogues) --------------------------------
#define TILE_STRIDE 144
#define ST          (128*TILE_STRIDE)
#define G_SMEM_BYTES (4*ST)

__global__ __launch_bounds__(256, 2)
void gemm_mma(const __nv_bfloat16* __restrict__ A,
              const __nv_bfloat16* __restrict__ Wq,
              const __nv_bfloat16* __restrict__ Wk,
              const __nv_bfloat16* __restrict__ Wv,
              float* __restrict__ Dout, int fused)
{
    extern __shared__ char smem[];
    uint32_t sb = smem_u32(smem);
    int tid = threadIdx.x, wid = tid >> 5, lane = tid & 31;
    int warpm = wid >> 2, warpn = wid & 3;
    int lrw = lane >> 2, lk = lane & 3;

    const __nv_bfloat16* W; int n0, mode;
    if (fused) {
        int which = blockIdx.x >> 4;
        n0 = (blockIdx.x & 15) * 128;
        W = (which == 0) ? Wq : (which == 1) ? Wk : Wv;
        mode = which;
    } else { n0 = blockIdx.x * 128; W = Wq; mode = 3; }
    int m0 = blockIdx.y * 128;

    const char* Ab = (const char*)(A + (size_t)m0 * K3);
    const char* Bb = (const char*)(W + (size_t)n0 * K3);

    float acc[4][4][4];
    #pragma unroll
    for (int i = 0; i < 4; i++)
        #pragma unroll
        for (int j = 0; j < 4; j++)
            #pragma unroll
            for (int r = 0; r < 4; r++) acc[i][j][r] = 0.f;

    int ld_r = tid >> 1, ld_c = (tid & 1) * 64;
    auto issue_stage = [&](int kelem, int buf) {
        uint32_t sA = sb + buf * ST + ld_r * TILE_STRIDE + ld_c;
        uint32_t sB = sA + 2 * ST;
        const char* gA = Ab + (size_t)kelem * 2 + (size_t)ld_r * (K3 * 2) + ld_c;
        const char* gB = Bb + (size_t)kelem * 2 + (size_t)ld_r * (K3 * 2) + ld_c;
        #pragma unroll
        for (int j = 0; j < 4; j++) {
            cp_async16(sA + j * 16, gA + j * 16);
            cp_async16(sB + j * 16, gB + j * 16);
        }
        CP_COMMIT();
    };
    uint32_t aOff = (uint32_t)((warpm * 64 + (lane & 15)) * TILE_STRIDE + ((lane >> 4) << 4));
    uint32_t bOff = (uint32_t)((warpn * 32 + (lane & 7) + ((lane >> 4) << 3)) * TILE_STRIDE
                               + (((lane >> 3) & 1) << 4));
    issue_stage(0, 0);
    for (int st = 0; st < NSTAGE; st++) {
        if (st + 1 < NSTAGE) { issue_stage((st + 1) * BK, (st + 1) & 1); CP_WAIT(1); }
        else                 { CP_WAIT(0); }
        __syncthreads();
        uint32_t aB = sb + (st & 1) * ST + aOff;
        uint32_t bB = sb + 2 * ST + (st & 1) * ST + bOff;
        #pragma unroll
        for (int s = 0; s < 4; s++) {
            uint32_t af[4][4], bf[4][2];
            #pragma unroll
            for (int i = 0; i < 4; i++)
                LDMX4(af[i][0], af[i][1], af[i][2], af[i][3],
                      aB + i * 16 * TILE_STRIDE + s * 32);
            #pragma unroll
            for (int p = 0; p < 2; p++) {
                uint32_t r0, r1, r2, r3;
                LDMX4(r0, r1, r2, r3, bB + p * 16 * TILE_STRIDE + s * 32);
                bf[2*p][0] = r0; bf[2*p][1] = r1; bf[2*p+1][0] = r2; bf[2*p+1][1] = r3;
            }
            #pragma unroll
            for (int i = 0; i < 4; i++)
                #pragma unroll
                for (int j = 0; j < 4; j++)
                    mma16816(acc[i][j], af[i], bf[j]);
        }
        __syncthreads();
    }

    float* Osm = (float*)smem;
    #pragma unroll
    for (int i = 0; i < 4; i++) {
        int r0 = warpm * 64 + i * 16 + lrw;
        #pragma unroll
        for (int j = 0; j < 4; j++) {
            int c0 = warpn * 32 + j * 8 + lk * 2;
            Osm[r0 * 132 + c0]           = acc[i][j][0];
            Osm[r0 * 132 + c0 + 1]       = acc[i][j][1];
            Osm[(r0 + 8) * 132 + c0]     = acc[i][j][2];
            Osm[(r0 + 8) * 132 + c0 + 1] = acc[i][j][3];
        }
    }
    __syncthreads();

    if (mode == 3) {
        #pragma unroll
        for (int it = 0; it < 16; it++) {
            int f = it * 256 + tid;
            int r = f >> 5, c4 = (f & 31) << 2;
            float4 v = *(float4*)&Osm[r * 132 + c4];
            *(float4*)&Dout[(size_t)(m0 + r) * HIDDEN + n0 + c4] = v;
        }
    } else if (mode <= 1) {
        int h = (n0 >> 7) & 15;
        const float scale = (mode == 0) ? 0.08838834764831845f : 1.0f;
        __nv_bfloat16* dst = (mode == 0) ? g_qp : g_kp;
        #pragma unroll
        for (int it = 0; it < 32; it++) {
            int f = it * 256 + tid;
            int r = f >> 6, i = f & 63;
            int m = m0 + r;
            int b = m >> 11, s = m & (SEQ - 1);
            float x1 = Osm[r * 132 + i], x2 = Osm[r * 132 + i + 64];
            float c = g_cos[s * 64 + i], sn = g_sin[s * 64 + i];
            float o1 = (x1 * c - x2 * sn) * scale;
            float o2 = (x2 * c + x1 * sn) * scale;
            __nv_bfloat16 h1 = __float2bfloat16(o1), h2 = __float2bfloat16(o2);
            __nv_bfloat16 l1 = __float2bfloat16(o1 - __bfloat162float(h1));
            __nv_bfloat16 l2 = __float2bfloat16(o2 - __bfloat162float(h2));
            size_t base = ((size_t)(b * HEADS + h) * SEQ + s) * 256;
            dst[base + i] = h1; dst[base + i + 64] = h2;
            dst[base + 128 + i] = l1; dst[base + 128 + i + 64] = l2;
        }
    } else {
        int h = (n0 >> 7) & 15;
        #pragma unroll
        for (int it = 0; it < 64; it++) {
            int f = it * 256 + tid;
            int mloc = f & 127, d = (f >> 7) & 127;
            float val = Osm[mloc * 132 + d];
            int m = m0 + mloc;
            int b = m >> 11, s = m & (SEQ - 1);
            __nv_bfloat16 hv = __float2bfloat16(val);
            __nv_bfloat16 lv = __float2bfloat16(val - __bfloat162float(hv));
            size_t o = ((size_t)((b * HEADS + h) * HD + d)) * SEQ + s;
            g_vh[o] = hv; g_vl[o] = lv;
        }
    }
}

// ------------- tensor-core flash attention -----------------------------------
#define AQ_STR 528
#define AK_STR 528
#define AV_STR 272
#define AOFF_K (128*AQ_STR)
#define AK_SZ  (64*AK_STR)
#define AOFF_V (AOFF_K + 2*AK_SZ)
#define AV_SZ  (128*AV_STR)
#define ATTN_SMEM (AOFF_V + 2*AV_SZ)
#define NEGB   -1e30f

__global__ __launch_bounds__(256, 1)
void attn_kernel()
{
    extern __shared__ char sm[];
    uint32_t sb = smem_u32(sm);
    int tid = threadIdx.x, wid = tid >> 5, lane = tid & 31;
    int lrw = lane >> 2, lk = lane & 3;
    int qt = 15 - blockIdx.x;
    int bh = blockIdx.y;

    // Q tile: 128 rows x 512B
    {
        int r = tid >> 1, c0 = (tid & 1) * 256;
        uint32_t s = sb + r * AQ_STR + c0;
        const char* g = (const char*)g_qp + ((size_t)bh * SEQ + (size_t)qt * 128 + r) * 512 + c0;
        #pragma unroll
        for (int j = 0; j < 16; j++) cp_async16(s + j * 16, g + j * 16);
        CP_COMMIT();
    }
    int kr = tid >> 2, kc = (tid & 3) * 128;
    int vr = tid >> 1, vh = tid & 1;
    auto issue_kv = [&](int kt, int buf) {
        uint32_t s = sb + AOFF_K + buf * AK_SZ + kr * AK_STR + kc;
        const char* g = (const char*)g_kp + ((size_t)bh * SEQ + (size_t)kt * 64 + kr) * 512 + kc;
        #pragma unroll
        for (int j = 0; j < 8; j++) cp_async16(s + j * 16, g + j * 16);
        uint32_t sv = sb + AOFF_V + buf * AV_SZ + vr * AV_STR + vh * 128;
        const __nv_bfloat16* vg = (vh ? g_vl : g_vh) + ((size_t)bh * HD + vr) * SEQ + (size_t)kt * 64;
        #pragma unroll
        for (int j = 0; j < 8; j++) cp_async16(sv + j * 16, (const char*)vg + j * 16);
        CP_COMMIT();
    };

    float accO[16][4];
    #pragma unroll
    for (int nt = 0; nt < 16; nt++)
        #pragma unroll
        for (int r = 0; r < 4; r++) accO[nt][r] = 0.f;
    float mA = NEGB, mB = NEGB, lA = 0.f, lB = 0.f;

    uint32_t qfb = sb + (wid * 16 + (lane & 15)) * AQ_STR + ((lane >> 4) << 4);
    uint32_t kfo = (uint32_t)(((lane & 7) + ((lane >> 4) << 3)) * AK_STR + (((lane >> 3) & 1) << 4));
    uint32_t vfo = (uint32_t)(((lane & 7) + ((lane >> 4) << 3)) * AV_STR + (((lane >> 3) & 1) << 4));
    int rgA = qt * 128 + wid * 16 + lrw;
    int nkt = 2 * qt + 2;

    issue_kv(0, 0);
    for (int kt = 0; kt < nkt; kt++) {
        if (kt + 1 < nkt) { issue_kv(kt + 1, (kt + 1) & 1); CP_WAIT(1); }
        else              { CP_WAIT(0); }
        __syncthreads();

        if (kt * 64 <= qt * 128 + wid * 16 + 15) {
            float sacc[8][4];
            #pragma unroll
            for (int nt = 0; nt < 8; nt++)
                #pragma unroll
                for (int r = 0; r < 4; r++) sacc[nt][r] = 0.f;

            uint32_t kbuf = sb + AOFF_K + (kt & 1) * AK_SZ + kfo;
            #pragma unroll
            for (int pass = 0; pass < 3; pass++) {
                uint32_t qo = qfb + (pass == 2 ? 256u : 0u);
                uint32_t ko = kbuf + (pass == 1 ? 256u : 0u);
                #pragma unroll
                for (int ks = 0; ks < 8; ks++) {
                    uint32_t af[4];
                    LDMX4(af[0], af[1], af[2], af[3], qo + ks * 32);
                    #pragma unroll
                    for (int np = 0; np < 4; np++) {
                        uint32_t b0, b1, b2, b3;
                        LDMX4(b0, b1, b2, b3, ko + np * 16 * AK_STR + ks * 32);
                        uint32_t bf0[2] = {b0, b1}, bf1[2] = {b2, b3};
                        mma16816(sacc[2*np],   af, bf0);
                        mma16816(sacc[2*np+1], af, bf1);
                    }
                }
            }
            // causal mask
            if (kt * 64 + 63 > qt * 128 + wid * 16) {
                #pragma unroll
                for (int nt = 0; nt < 8; nt++) {
                    int cg = kt * 64 + nt * 8 + 2 * lk;
                    if (cg     > rgA)     sacc[nt][0] = NEGB;
                    if (cg + 1 > rgA)     sacc[nt][1] = NEGB;
                    if (cg     > rgA + 8) sacc[nt][2] = NEGB;
                    if (cg + 1 > rgA + 8) sacc[nt][3] = NEGB;
                }
            }
            // warp-local online softmax
            float nmA = mA, nmB = mB;
            #pragma unroll
            for (int nt = 0; nt < 8; nt++) {
                nmA = fmaxf(nmA, fmaxf(sacc[nt][0], sacc[nt][1]));
                nmB = fmaxf(nmB, fmaxf(sacc[nt][2], sacc[nt][3]));
            }
            nmA = fmaxf(nmA, __shfl_xor_sync(~0u, nmA, 1));
            nmA = fmaxf(nmA, __shfl_xor_sync(~0u, nmA, 2));
            nmB = fmaxf(nmB, __shfl_xor_sync(~0u, nmB, 1));
            nmB = fmaxf(nmB, __shfl_xor_sync(~0u, nmB, 2));
            float coA = __expf(mA - nmA), coB = __expf(mB - nmB);
            mA = nmA; mB = nmB;
            float sumA = 0.f, sumB = 0.f;
            #pragma unroll
            for (int nt = 0; nt < 8; nt++) {
                sacc[nt][0] = __expf(sacc[nt][0] - nmA);
                sacc[nt][1] = __expf(sacc[nt][1] - nmA);
                sacc[nt][2] = __expf(sacc[nt][2] - nmB);
                sacc[nt][3] = __expf(sacc[nt][3] - nmB);
                sumA += sacc[nt][0] + sacc[nt][1];
                sumB += sacc[nt][2] + sacc[nt][3];
            }
            sumA += __shfl_xor_sync(~0u, sumA, 1);
            sumA += __shfl_xor_sync(~0u, sumA, 2);
            sumB += __shfl_xor_sync(~0u, sumB, 1);
            sumB += __shfl_xor_sync(~0u, sumB, 2);
            lA = lA * coA + sumA;
            lB = lB * coB + sumB;
            #pragma unroll
            for (int nt = 0; nt < 16; nt++) {
                accO[nt][0] *= coA; accO[nt][1] *= coA;
                accO[nt][2] *= coB; accO[nt][3] *= coB;
            }
            // P fragments (hi + lo) from score C-fragments
            uint32_t phi[4][4], plo[4][4];
            #pragma unroll
            for (int s = 0; s < 4; s++) {
                #pragma unroll
                for (int half = 0; half < 2; half++) {
                    int nt = 2 * s + half;
                    float p0 = sacc[nt][0], p1 = sacc[nt][1];
                    float p2 = sacc[nt][2], p3 = sacc[nt][3];
                    PACK_BF2(phi[s][2*half],   p0, p1);
                    PACK_BF2(phi[s][2*half+1], p2, p3);
                    float r0 = p0 - __bfloat162float(__float2bfloat16(p0));
                    float r1 = p1 - __bfloat162float(__float2bfloat16(p1));
                    float r2 = p2 - __bfloat162float(__float2bfloat16(p2));
                    float r3 = p3 - __bfloat162float(__float2bfloat16(p3));
                    PACK_BF2(plo[s][2*half],   r0, r1);
                    PACK_BF2(plo[s][2*half+1], r2, r3);
                }
            }
            // P @ V^T: 3 passes
            uint32_t vbuf = sb + AOFF_V + (kt & 1) * AV_SZ + vfo;
            #pragma unroll
            for (int ks = 0; ks < 4; ks++) {
                #pragma unroll
                for (int nt16 = 0; nt16 < 8; nt16++) {
                    uint32_t base = vbuf + nt16 * 16 * AV_STR + ks * 32;
                    uint32_t h0, h1, h2, h3, l0, l1, l2, l3;
                    LDMX4(h0, h1, h2, h3, base);
                    LDMX4(l0, l1, l2, l3, base + 128);
                    uint32_t bh0[2] = {h0, h1}, bh1[2] = {h2, h3};
                    uint32_t bl0[2] = {l0, l1}, bl1[2] = {l2, l3};
                    mma16816(accO[2*nt16],   phi[ks], bh0);
                    mma16816(accO[2*nt16+1], phi[ks], bh1);
                    mma16816(accO[2*nt16],   phi[ks], bl0);
                    mma16816(accO[2*nt16+1], phi[ks], bl1);
                    mma16816(accO[2*nt16],   plo[ks], bh0);
                    mma16816(accO[2*nt16+1], plo[ks], bh1);
                }
            }
        }
        __syncthreads();
    }

    // epilogue: normalize -> smem stage -> bf16x3 split write
    float iA = 1.f / lA, iB = 1.f / lB;
    float* Osm = (float*)sm;
    int r0 = wid * 16 + lrw;
    #pragma unroll
    for (int nt = 0; nt < 16; nt++) {
        int c = nt * 8 + 2 * lk;
        *(float2*)&Osm[r0 * 132 + c]       = make_float2(accO[nt][0] * iA, accO[nt][1] * iA);
        *(float2*)&Osm[(r0 + 8) * 132 + c] = make_float2(accO[nt][2] * iB, accO[nt][3] * iB);
    }
    __syncthreads();
    int bb = bh >> 4, h = bh & 15;
    #pragma unroll
    for (int it = 0; it < 32; it++) {
        int f = it * 256 + tid;
        int r = f >> 6, d2 = (f & 63) * 2;
        float v0 = Osm[r * 132 + d2], v1 = Osm[r * 132 + d2 + 1];
        __nv_bfloat16 hb[2] = {__float2bfloat16(v0), __float2bfloat16(v1)};
        __nv_bfloat16 lb[2] = {__float2bfloat16(v0 - __bfloat162float(hb[0])),
                               __float2bfloat16(v1 - __bfloat162float(hb[1]))};
        size_t row = (size_t)bb * SEQ + (size_t)qt * 128 + r;
        __nv_bfloat16* dp = g_Cp + row * K3 + h * 128 + d2;
        uint32_t hp = *(uint32_t*)hb, lp = *(uint32_t*)lb;
        *(uint32_t*)dp = hp;
        *(uint32_t*)(dp + HIDDEN) = hp;
        *(uint32_t*)(dp + 2 * HIDDEN) = lp;
    }
}

// ------------- launcher -------------------------------------------------------
extern "C" void kernel_launch(void* const* d_in, const int* in_sizes, int n_in,
                              void* d_out, int out_size)
{
    (void)in_sizes; (void)n_in; (void)out_size;
    const float* X  = (const float*)d_in[0];
    const float* wq = (const float*)d_in[1];
    const float* wk = (const float*)d_in[2];
    const float* wv = (const float*)d_in[3];
    const float* wo = (const float*)d_in[4];
    float* out = (float*)d_out;

    __nv_bfloat16 *xp, *wp, *cp;
    cudaGetSymbolAddress((void**)&xp, g_Xp);
    cudaGetSymbolAddress((void**)&wp, g_Wp);
    cudaGetSymbolAddress((void**)&cp, g_Cp);
    __nv_bfloat16* wps[4];
    for (int i = 0; i < 4; i++) wps[i] = wp + (size_t)i * HIDDEN * K3;

    cudaFuncSetAttribute(gemm_mma, cudaFuncAttributeMaxDynamicSharedMemorySize, G_SMEM_BYTES);
    cudaFuncSetAttribute(attn_kernel, cudaFuncAttributeMaxDynamicSharedMemorySize, ATTN_SMEM);

    rope_table_kernel<<<(SEQ * 64 + 255) / 256, 256>>>();

    convert_split<<<(MTOT * HIDDEN / 4 + 255) / 256, 256>>>(X,  xp,     MTOT,   0);
    convert_split<<<(HIDDEN * HIDDEN / 4 + 255) / 256, 256>>>(wq, wps[0], HIDDEN, 1);
    convert_split<<<(HIDDEN * HIDDEN / 4 + 255) / 256, 256>>>(wk, wps[1], HIDDEN, 1);
    convert_split<<<(HIDDEN * HIDDEN / 4 + 255) / 256, 256>>>(wv, wps[2], HIDDEN, 1);
    convert_split<<<(HIDDEN * HIDDEN / 4 + 255) / 256, 256>>>(wo, wps[3], HIDDEN, 1);

    gemm_mma<<<dim3(48, 32), 256, G_SMEM_BYTES>>>(xp, wps[0], wps[1], wps[2], out, 1);

    attn_kernel<<<dim3(16, NB * HEADS), 256, ATTN_SMEM>>>();

    gemm_mma<<<dim3(16, 32), 256, G_SMEM_BYTES>>>(cp, wps[3], wps[3], wps[3], out, 0);
}

// round 7
// speedup vs baseline: 1.3049x; 1.0500x over previous
#include <cuda_runtime.h>
#include <cuda_bf16.h>
#include <cstdint>

#define HIDDEN 2048
#define K3     6144
#define HEADS  16
#define HD     128
#define NB     2
#define SEQ    2048
#define MTOT   4096
#define BK     64
#define NSTAGE (K3/BK)

__device__ __align__(128) __nv_bfloat16 g_Xp[(size_t)MTOT*K3];
__device__ __align__(128) __nv_bfloat16 g_Wp[4][(size_t)HIDDEN*K3];
__device__ __align__(128) __nv_bfloat16 g_Cp[(size_t)MTOT*K3];
__device__ __align__(128) __nv_bfloat16 g_qp[(size_t)NB*HEADS*SEQ*256];  // [bh][s][hi128|lo128]
__device__ __align__(128) __nv_bfloat16 g_kp[(size_t)NB*HEADS*SEQ*256];
__device__ __align__(128) __nv_bfloat16 g_vh[(size_t)NB*HEADS*HD*SEQ];   // [bh][d][s]
__device__ __align__(128) __nv_bfloat16 g_vl[(size_t)NB*HEADS*HD*SEQ];
__device__ float g_cos[SEQ*64];
__device__ float g_sin[SEQ*64];

__device__ __forceinline__ void mma16816(float* c, const uint32_t* a, const uint32_t* b) {
    asm volatile(
        "mma.sync.aligned.m16n8k16.row.col.f32.bf16.bf16.f32 "
        "{%0,%1,%2,%3}, {%4,%5,%6,%7}, {%8,%9}, {%0,%1,%2,%3};"
        : "+f"(c[0]), "+f"(c[1]), "+f"(c[2]), "+f"(c[3])
        : "r"(a[0]), "r"(a[1]), "r"(a[2]), "r"(a[3]), "r"(b[0]), "r"(b[1]));
}
__device__ __forceinline__ void cp_async16(uint32_t saddr, const void* gaddr) {
    asm volatile("cp.async.ca.shared.global [%0], [%1], 16;" :: "r"(saddr), "l"(gaddr));
}
#define CP_COMMIT() asm volatile("cp.async.commit_group;" ::: "memory")
#define CP_WAIT(n)  asm volatile("cp.async.wait_group %0;" :: "n"(n) : "memory")
#define LDMX4(d0,d1,d2,d3,addr) \
    asm volatile("ldmatrix.sync.aligned.m8n8.x4.shared.b16 {%0,%1,%2,%3}, [%4];" \
                 : "=r"(d0), "=r"(d1), "=r"(d2), "=r"(d3) : "r"(addr))
#define PACK_BF2(dst, flo, fhi) \
    asm("cvt.rn.bf16x2.f32 %0, %1, %2;" : "=r"(dst) : "f"(fhi), "f"(flo))
__device__ __forceinline__ uint32_t smem_u32(const void* p) {
    uint32_t a;
    asm("{ .reg .u64 t; cvta.to.shared.u64 t, %1; cvt.u32.u64 %0, t; }" : "=r"(a) : "l"(p));
    return a;
}

__global__ void rope_table_kernel() {
    int idx = blockIdx.x * blockDim.x + threadIdx.x;
    if (idx >= SEQ * 64) return;
    int s = idx >> 6, i = idx & 63;
    double invf = pow(10000.0, -(double)i / 64.0);
    double ang = (double)s * invf;
    g_cos[idx] = (float)cos(ang);
    g_sin[idx] = (float)sin(ang);
}

// X split: [k]=hi, [2048+k]=hi, [4096+k]=lo
__global__ void convert_x(const float* __restrict__ src) {
    long idx = (long)blockIdx.x * blockDim.x + threadIdx.x;
    if (idx >= (long)MTOT * (HIDDEN / 4)) return;
    long r = idx >> 9;
    int k = (int)(idx & 511) << 2;
    float4 x = ((const float4*)src)[idx];
    __nv_bfloat16 hv[4] = {__float2bfloat16(x.x), __float2bfloat16(x.y),
                           __float2bfloat16(x.z), __float2bfloat16(x.w)};
    __nv_bfloat16 lv[4] = {__float2bfloat16(x.x - __bfloat162float(hv[0])),
                           __float2bfloat16(x.y - __bfloat162float(hv[1])),
                           __float2bfloat16(x.z - __bfloat162float(hv[2])),
                           __float2bfloat16(x.w - __bfloat162float(hv[3]))};
    __nv_bfloat16* d = g_Xp + r * K3;
    uint2 hp = *(uint2*)hv, lp = *(uint2*)lv;
    *(uint2*)&d[k] = hp;
    *(uint2*)&d[HIDDEN + k] = hp;
    *(uint2*)&d[2 * HIDDEN + k] = lp;
}

// all 4 weights, one launch. W split: [k]=hi, [2048+k]=lo, [4096+k]=hi
__global__ void convert_w4(const float* __restrict__ w0, const float* __restrict__ w1,
                           const float* __restrict__ w2, const float* __restrict__ w3) {
    long idx = (long)blockIdx.x * blockDim.x + threadIdx.x;
    const long per = (long)HIDDEN * (HIDDEN / 4);
    if (idx >= 4 * per) return;
    int which = (int)(idx / per);
    long li = idx - (long)which * per;
    const float* src = (which == 0) ? w0 : (which == 1) ? w1 : (which == 2) ? w2 : w3;
    long r = li >> 9;
    int k = (int)(li & 511) << 2;
    float4 x = ((const float4*)src)[li];
    __nv_bfloat16 hv[4] = {__float2bfloat16(x.x), __float2bfloat16(x.y),
                           __float2bfloat16(x.z), __float2bfloat16(x.w)};
    __nv_bfloat16 lv[4] = {__float2bfloat16(x.x - __bfloat162float(hv[0])),
                           __float2bfloat16(x.y - __bfloat162float(hv[1])),
                           __float2bfloat16(x.z - __bfloat162float(hv[2])),
                           __float2bfloat16(x.w - __bfloat162float(hv[3]))};
    __nv_bfloat16* d = g_Wp[which] + r * K3;
    uint2 hp = *(uint2*)hv, lp = *(uint2*)lv;
    *(uint2*)&d[k] = hp;
    *(uint2*)&d[HIDDEN + k] = lp;
    *(uint2*)&d[2 * HIDDEN + k] = hp;
}

// ------------- GEMM ----------------------------------------------------------
#define TILE_STRIDE 144
#define ST          (128*TILE_STRIDE)
#define G_SMEM_BYTES (4*ST)

__global__ __launch_bounds__(256, 2)
void gemm_mma(const __nv_bfloat16* __restrict__ A,
              const __nv_bfloat16* __restrict__ Wq,
              const __nv_bfloat16* __restrict__ Wk,
              const __nv_bfloat16* __restrict__ Wv,
              float* __restrict__ Dout, int fused)
{
    extern __shared__ char smem[];
    uint32_t sb = smem_u32(smem);
    int tid = threadIdx.x, wid = tid >> 5, lane = tid & 31;
    int warpm = wid >> 2, warpn = wid & 3;
    int lrw = lane >> 2, lk = lane & 3;

    const __nv_bfloat16* W; int n0, mode;
    if (fused) {
        int which = blockIdx.x >> 4;
        n0 = (blockIdx.x & 15) * 128;
        W = (which == 0) ? Wq : (which == 1) ? Wk : Wv;
        mode = which;
    } else { n0 = blockIdx.x * 128; W = Wq; mode = 3; }
    int m0 = blockIdx.y * 128;

    const char* Ab = (const char*)(A + (size_t)m0 * K3);
    const char* Bb = (const char*)(W + (size_t)n0 * K3);

    float acc[4][4][4];
    #pragma unroll
    for (int i = 0; i < 4; i++)
        #pragma unroll
        for (int j = 0; j < 4; j++)
            #pragma unroll
            for (int r = 0; r < 4; r++) acc[i][j][r] = 0.f;

    int ld_r = tid >> 1, ld_c = (tid & 1) * 64;
    auto issue_stage = [&](int kelem, int buf) {
        uint32_t sA = sb + buf * ST + ld_r * TILE_STRIDE + ld_c;
        uint32_t sB = sA + 2 * ST;
        const char* gA = Ab + (size_t)kelem * 2 + (size_t)ld_r * (K3 * 2) + ld_c;
        const char* gB = Bb + (size_t)kelem * 2 + (size_t)ld_r * (K3 * 2) + ld_c;
        #pragma unroll
        for (int j = 0; j < 4; j++) {
            cp_async16(sA + j * 16, gA + j * 16);
            cp_async16(sB + j * 16, gB + j * 16);
        }
        CP_COMMIT();
    };
    uint32_t aOff = (uint32_t)((warpm * 64 + (lane & 15)) * TILE_STRIDE + ((lane >> 4) << 4));
    uint32_t bOff = (uint32_t)((warpn * 32 + (lane & 7) + ((lane >> 4) << 3)) * TILE_STRIDE
                               + (((lane >> 3) & 1) << 4));
    issue_stage(0, 0);
    for (int st = 0; st < NSTAGE; st++) {
        if (st + 1 < NSTAGE) { issue_stage((st + 1) * BK, (st + 1) & 1); CP_WAIT(1); }
        else                 { CP_WAIT(0); }
        __syncthreads();
        uint32_t aB = sb + (st & 1) * ST + aOff;
        uint32_t bB = sb + 2 * ST + (st & 1) * ST + bOff;
        #pragma unroll
        for (int s = 0; s < 4; s++) {
            uint32_t af[4][4], bf[4][2];
            #pragma unroll
            for (int i = 0; i < 4; i++)
                LDMX4(af[i][0], af[i][1], af[i][2], af[i][3],
                      aB + i * 16 * TILE_STRIDE + s * 32);
            #pragma unroll
            for (int p = 0; p < 2; p++) {
                uint32_t r0, r1, r2, r3;
                LDMX4(r0, r1, r2, r3, bB + p * 16 * TILE_STRIDE + s * 32);
                bf[2*p][0] = r0; bf[2*p][1] = r1; bf[2*p+1][0] = r2; bf[2*p+1][1] = r3;
            }
            #pragma unroll
            for (int i = 0; i < 4; i++)
                #pragma unroll
                for (int j = 0; j < 4; j++)
                    mma16816(acc[i][j], af[i], bf[j]);
        }
        __syncthreads();
    }

    float* Osm = (float*)smem;
    #pragma unroll
    for (int i = 0; i < 4; i++) {
        int r0 = warpm * 64 + i * 16 + lrw;
        #pragma unroll
        for (int j = 0; j < 4; j++) {
            int c0 = warpn * 32 + j * 8 + lk * 2;
            Osm[r0 * 132 + c0]           = acc[i][j][0];
            Osm[r0 * 132 + c0 + 1]       = acc[i][j][1];
            Osm[(r0 + 8) * 132 + c0]     = acc[i][j][2];
            Osm[(r0 + 8) * 132 + c0 + 1] = acc[i][j][3];
        }
    }
    __syncthreads();

    if (mode == 3) {
        #pragma unroll
        for (int it = 0; it < 16; it++) {
            int f = it * 256 + tid;
            int r = f >> 5, c4 = (f & 31) << 2;
            float4 v = *(float4*)&Osm[r * 132 + c4];
            *(float4*)&Dout[(size_t)(m0 + r) * HIDDEN + n0 + c4] = v;
        }
    } else if (mode <= 1) {
        int h = (n0 >> 7) & 15;
        const float scale = (mode == 0) ? 0.08838834764831845f : 1.0f;
        __nv_bfloat16* dst = (mode == 0) ? g_qp : g_kp;
        #pragma unroll
        for (int it = 0; it < 32; it++) {
            int f = it * 256 + tid;
            int r = f >> 6, i = f & 63;
            int m = m0 + r;
            int b = m >> 11, s = m & (SEQ - 1);
            float x1 = Osm[r * 132 + i], x2 = Osm[r * 132 + i + 64];
            float c = g_cos[s * 64 + i], sn = g_sin[s * 64 + i];
            float o1 = (x1 * c - x2 * sn) * scale;
            float o2 = (x2 * c + x1 * sn) * scale;
            __nv_bfloat16 h1 = __float2bfloat16(o1), h2 = __float2bfloat16(o2);
            __nv_bfloat16 l1 = __float2bfloat16(o1 - __bfloat162float(h1));
            __nv_bfloat16 l2 = __float2bfloat16(o2 - __bfloat162float(h2));
            size_t base = ((size_t)(b * HEADS + h) * SEQ + s) * 256;
            dst[base + i] = h1; dst[base + i + 64] = h2;
            dst[base + 128 + i] = l1; dst[base + 128 + i + 64] = l2;
        }
    } else {
        int h = (n0 >> 7) & 15;
        #pragma unroll
        for (int it = 0; it < 64; it++) {
            int f = it * 256 + tid;
            int mloc = f & 127, d = (f >> 7) & 127;
            float val = Osm[mloc * 132 + d];
            int m = m0 + mloc;
            int b = m >> 11, s = m & (SEQ - 1);
            __nv_bfloat16 hv = __float2bfloat16(val);
            __nv_bfloat16 lv = __float2bfloat16(val - __bfloat162float(hv));
            size_t o = ((size_t)((b * HEADS + h) * HD + d)) * SEQ + s;
            g_vh[o] = hv; g_vl[o] = lv;
        }
    }
}

// ------------- tensor-core flash attention -----------------------------------
#define AQ_STR 528
#define AK_STR 528
#define AV_STR 272
#define AOFF_K (128*AQ_STR)
#define AK_SZ  (64*AK_STR)
#define AOFF_V (AOFF_K + 2*AK_SZ)
#define AV_SZ  (128*AV_STR)
#define ATTN_SMEM (AOFF_V + 2*AV_SZ)
#define NEGB   -1e30f

__global__ __launch_bounds__(256, 1)
void attn_kernel()
{
    extern __shared__ char sm[];
    uint32_t sb = smem_u32(sm);
    int tid = threadIdx.x, wid = tid >> 5, lane = tid & 31;
    int lrw = lane >> 2, lk = lane & 3;
    // heavy-first linear schedule: all qt=15 CTAs dispatch first
    int qt = 15 - (blockIdx.x >> 5);
    int bh = blockIdx.x & 31;

    {
        int r = tid >> 1, c0 = (tid & 1) * 256;
        uint32_t s = sb + r * AQ_STR + c0;
        const char* g = (const char*)g_qp + ((size_t)bh * SEQ + (size_t)qt * 128 + r) * 512 + c0;
        #pragma unroll
        for (int j = 0; j < 16; j++) cp_async16(s + j * 16, g + j * 16);
        CP_COMMIT();
    }
    int kr = tid >> 2, kc = (tid & 3) * 128;
    int vr = tid >> 1, vh = tid & 1;
    auto issue_kv = [&](int kt, int buf) {
        uint32_t s = sb + AOFF_K + buf * AK_SZ + kr * AK_STR + kc;
        const char* g = (const char*)g_kp + ((size_t)bh * SEQ + (size_t)kt * 64 + kr) * 512 + kc;
        #pragma unroll
        for (int j = 0; j < 8; j++) cp_async16(s + j * 16, g + j * 16);
        uint32_t sv = sb + AOFF_V + buf * AV_SZ + vr * AV_STR + vh * 128;
        const __nv_bfloat16* vg = (vh ? g_vl : g_vh) + ((size_t)bh * HD + vr) * SEQ + (size_t)kt * 64;
        #pragma unroll
        for (int j = 0; j < 8; j++) cp_async16(sv + j * 16, (const char*)vg + j * 16);
        CP_COMMIT();
    };

    float accO[16][4];
    #pragma unroll
    for (int nt = 0; nt < 16; nt++)
        #pragma unroll
        for (int r = 0; r < 4; r++) accO[nt][r] = 0.f;
    float mA = NEGB, mB = NEGB, lA = 0.f, lB = 0.f;

    uint32_t qfb = sb + (wid * 16 + (lane & 15)) * AQ_STR + ((lane >> 4) << 4);
    uint32_t kfo = (uint32_t)(((lane & 7) + ((lane >> 4) << 3)) * AK_STR + (((lane >> 3) & 1) << 4));
    uint32_t vfo = (uint32_t)(((lane & 7) + ((lane >> 4) << 3)) * AV_STR + (((lane >> 3) & 1) << 4));
    int rgA = qt * 128 + wid * 16 + lrw;
    int nkt = 2 * qt + 2;

    issue_kv(0, 0);
    for (int kt = 0; kt < nkt; kt++) {
        if (kt + 1 < nkt) { issue_kv(kt + 1, (kt + 1) & 1); CP_WAIT(1); }
        else              { CP_WAIT(0); }
        __syncthreads();

        if (kt * 64 <= qt * 128 + wid * 16 + 15) {
            float sacc[8][4];
            #pragma unroll
            for (int nt = 0; nt < 8; nt++)
                #pragma unroll
                for (int r = 0; r < 4; r++) sacc[nt][r] = 0.f;

            uint32_t kbuf = sb + AOFF_K + (kt & 1) * AK_SZ + kfo;
            #pragma unroll
            for (int pass = 0; pass < 3; pass++) {
                uint32_t qo = qfb + (pass == 2 ? 256u : 0u);
                uint32_t ko = kbuf + (pass == 1 ? 256u : 0u);
                #pragma unroll
                for (int ks = 0; ks < 8; ks++) {
                    uint32_t af[4];
                    LDMX4(af[0], af[1], af[2], af[3], qo + ks * 32);
                    #pragma unroll
                    for (int np = 0; np < 4; np++) {
                        uint32_t b0, b1, b2, b3;
                        LDMX4(b0, b1, b2, b3, ko + np * 16 * AK_STR + ks * 32);
                        uint32_t bf0[2] = {b0, b1}, bf1[2] = {b2, b3};
                        mma16816(sacc[2*np],   af, bf0);
                        mma16816(sacc[2*np+1], af, bf1);
                    }
                }
            }
            if (kt * 64 + 63 > qt * 128 + wid * 16) {
                #pragma unroll
                for (int nt = 0; nt < 8; nt++) {
                    int cg = kt * 64 + nt * 8 + 2 * lk;
                    if (cg     > rgA)     sacc[nt][0] = NEGB;
                    if (cg + 1 > rgA)     sacc[nt][1] = NEGB;
                    if (cg     > rgA + 8) sacc[nt][2] = NEGB;
                    if (cg + 1 > rgA + 8) sacc[nt][3] = NEGB;
                }
            }
            float nmA = mA, nmB = mB;
            #pragma unroll
            for (int nt = 0; nt < 8; nt++) {
                nmA = fmaxf(nmA, fmaxf(sacc[nt][0], sacc[nt][1]));
                nmB = fmaxf(nmB, fmaxf(sacc[nt][2], sacc[nt][3]));
            }
            nmA = fmaxf(nmA, __shfl_xor_sync(~0u, nmA, 1));
            nmA = fmaxf(nmA, __shfl_xor_sync(~0u, nmA, 2));
            nmB = fmaxf(nmB, __shfl_xor_sync(~0u, nmB, 1));
            nmB = fmaxf(nmB, __shfl_xor_sync(~0u, nmB, 2));
            float coA = __expf(mA - nmA), coB = __expf(mB - nmB);
            mA = nmA; mB = nmB;
            float sumA = 0.f, sumB = 0.f;
            #pragma unroll
            for (int nt = 0; nt < 8; nt++) {
                sacc[nt][0] = __expf(sacc[nt][0] - nmA);
                sacc[nt][1] = __expf(sacc[nt][1] - nmA);
                sacc[nt][2] = __expf(sacc[nt][2] - nmB);
                sacc[nt][3] = __expf(sacc[nt][3] - nmB);
                sumA += sacc[nt][0] + sacc[nt][1];
                sumB += sacc[nt][2] + sacc[nt][3];
            }
            sumA += __shfl_xor_sync(~0u, sumA, 1);
            sumA += __shfl_xor_sync(~0u, sumA, 2);
            sumB += __shfl_xor_sync(~0u, sumB, 1);
            sumB += __shfl_xor_sync(~0u, sumB, 2);
            lA = lA * coA + sumA;
            lB = lB * coB + sumB;
            #pragma unroll
            for (int nt = 0; nt < 16; nt++) {
                accO[nt][0] *= coA; accO[nt][1] *= coA;
                accO[nt][2] *= coB; accO[nt][3] *= coB;
            }
            uint32_t phi[4][4], plo[4][4];
            #pragma unroll
            for (int s = 0; s < 4; s++) {
                #pragma unroll
                for (int half = 0; half < 2; half++) {
                    int nt = 2 * s + half;
                    float p0 = sacc[nt][0], p1 = sacc[nt][1];
                    float p2 = sacc[nt][2], p3 = sacc[nt][3];
                    PACK_BF2(phi[s][2*half],   p0, p1);
                    PACK_BF2(phi[s][2*half+1], p2, p3);
                    float r0 = p0 - __bfloat162float(__float2bfloat16(p0));
                    float r1 = p1 - __bfloat162float(__float2bfloat16(p1));
                    float r2 = p2 - __bfloat162float(__float2bfloat16(p2));
                    float r3 = p3 - __bfloat162float(__float2bfloat16(p3));
                    PACK_BF2(plo[s][2*half],   r0, r1);
                    PACK_BF2(plo[s][2*half+1], r2, r3);
                }
            }
            // P @ V^T: pass-outer order (accO reuse distance = 16 mma)
            uint32_t vbuf = sb + AOFF_V + (kt & 1) * AV_SZ + vfo;
            #pragma unroll
            for (int pass = 0; pass < 3; pass++) {
                uint32_t voff = (pass == 1) ? 128u : 0u;
                #pragma unroll
                for (int ks = 0; ks < 4; ks++) {
                    const uint32_t* P = (pass == 2) ? plo[ks] : phi[ks];
                    #pragma unroll
                    for (int nt16 = 0; nt16 < 8; nt16++) {
                        uint32_t b0, b1, b2, b3;
                        LDMX4(b0, b1, b2, b3, vbuf + nt16 * 16 * AV_STR + ks * 32 + voff);
                        uint32_t bf0[2] = {b0, b1}, bf1[2] = {b2, b3};
                        mma16816(accO[2*nt16],   P, bf0);
                        mma16816(accO[2*nt16+1], P, bf1);
                    }
                }
            }
        }
        __syncthreads();
    }

    float iA = 1.f / lA, iB = 1.f / lB;
    float* Osm = (float*)sm;
    int r0 = wid * 16 + lrw;
    #pragma unroll
    for (int nt = 0; nt < 16; nt++) {
        int c = nt * 8 + 2 * lk;
        *(float2*)&Osm[r0 * 132 + c]       = make_float2(accO[nt][0] * iA, accO[nt][1] * iA);
        *(float2*)&Osm[(r0 + 8) * 132 + c] = make_float2(accO[nt][2] * iB, accO[nt][3] * iB);
    }
    __syncthreads();
    int bb = bh >> 4, h = bh & 15;
    #pragma unroll
    for (int it = 0; it < 32; it++) {
        int f = it * 256 + tid;
        int r = f >> 6, d2 = (f & 63) * 2;
        float v0 = Osm[r * 132 + d2], v1 = Osm[r * 132 + d2 + 1];
        __nv_bfloat16 hb[2] = {__float2bfloat16(v0), __float2bfloat16(v1)};
        __nv_bfloat16 lb[2] = {__float2bfloat16(v0 - __bfloat162float(hb[0])),
                               __float2bfloat16(v1 - __bfloat162float(hb[1]))};
        size_t row = (size_t)bb * SEQ + (size_t)qt * 128 + r;
        __nv_bfloat16* dp = g_Cp + row * K3 + h * 128 + d2;
        uint32_t hp = *(uint32_t*)hb, lp = *(uint32_t*)lb;
        *(uint32_t*)dp = hp;
        *(uint32_t*)(dp + HIDDEN) = hp;
        *(uint32_t*)(dp + 2 * HIDDEN) = lp;
    }
}

// ------------- launcher -------------------------------------------------------
extern "C" void kernel_launch(void* const* d_in, const int* in_sizes, int n_in,
                              void* d_out, int out_size)
{
    (void)in_sizes; (void)n_in; (void)out_size;
    const float* X  = (const float*)d_in[0];
    const float* wq = (const float*)d_in[1];
    const float* wk = (const float*)d_in[2];
    const float* wv = (const float*)d_in[3];
    const float* wo = (const float*)d_in[4];
    float* out = (float*)d_out;

    __nv_bfloat16 *xp, *wp, *cp;
    cudaGetSymbolAddress((void**)&xp, g_Xp);
    cudaGetSymbolAddress((void**)&wp, g_Wp);
    cudaGetSymbolAddress((void**)&cp, g_Cp);
    __nv_bfloat16* wps[4];
    for (int i = 0; i < 4; i++) wps[i] = wp + (size_t)i * HIDDEN * K3;

    cudaFuncSetAttribute(gemm_mma, cudaFuncAttributeMaxDynamicSharedMemorySize, G_SMEM_BYTES);
    cudaFuncSetAttribute(attn_kernel, cudaFuncAttributeMaxDynamicSharedMemorySize, ATTN_SMEM);

    rope_table_kernel<<<(SEQ * 64 + 255) / 256, 256>>>();

    convert_x<<<(MTOT * HIDDEN / 4 + 255) / 256, 256>>>(X);
    convert_w4<<<(4 * HIDDEN * (HIDDEN / 4) + 255) / 256, 256>>>(wq, wk, wv, wo);

    gemm_mma<<<dim3(48, 32), 256, G_SMEM_BYTES>>>(xp, wps[0], wps[1], wps[2], out, 1);

    attn_kernel<<<512, 256, ATTN_SMEM>>>();

    gemm_mma<<<dim3(16, 32), 256, G_SMEM_BYTES>>>(cp, wps[3], wps[3], wps[3], out, 0);
}

// round 8
// speedup vs baseline: 1.6158x; 1.2383x over previous
#include <cuda_runtime.h>
#include <cuda_bf16.h>
#include <cstdint>

#define HIDDEN 2048
#define HEADS  16
#define HD     128
#define NB     2
#define SEQ    2048
#define MTOT   4096
#define BK     32                 // true-K per stage
#define NSTAGE (HIDDEN/BK)        // 64

// ---------------- scratch ------------------------------------------------------
__device__ __align__(128) __nv_bfloat16 g_Ah[(size_t)MTOT*HIDDEN];
__device__ __align__(128) __nv_bfloat16 g_Al[(size_t)MTOT*HIDDEN];
__device__ __align__(128) __nv_bfloat16 g_Wh[4][(size_t)HIDDEN*HIDDEN];
__device__ __align__(128) __nv_bfloat16 g_Wl[4][(size_t)HIDDEN*HIDDEN];
__device__ __align__(128) __nv_bfloat16 g_Ch[(size_t)MTOT*HIDDEN];
__device__ __align__(128) __nv_bfloat16 g_Cl[(size_t)MTOT*HIDDEN];
__device__ __align__(128) __nv_bfloat16 g_qp[(size_t)NB*HEADS*SEQ*256];  // [bh][s][hi128|lo128]
__device__ __align__(128) __nv_bfloat16 g_kp[(size_t)NB*HEADS*SEQ*256];
__device__ __align__(128) __nv_bfloat16 g_vh[(size_t)NB*HEADS*HD*SEQ];   // [bh][d][s]
__device__ __align__(128) __nv_bfloat16 g_vl[(size_t)NB*HEADS*HD*SEQ];
__device__ float g_cos[SEQ*64];
__device__ float g_sin[SEQ*64];

__device__ __forceinline__ void mma16816(float* c, const uint32_t* a, const uint32_t* b) {
    asm volatile(
        "mma.sync.aligned.m16n8k16.row.col.f32.bf16.bf16.f32 "
        "{%0,%1,%2,%3}, {%4,%5,%6,%7}, {%8,%9}, {%0,%1,%2,%3};"
        : "+f"(c[0]), "+f"(c[1]), "+f"(c[2]), "+f"(c[3])
        : "r"(a[0]), "r"(a[1]), "r"(a[2]), "r"(a[3]), "r"(b[0]), "r"(b[1]));
}
__device__ __forceinline__ void cp_async16(uint32_t saddr, const void* gaddr) {
    asm volatile("cp.async.ca.shared.global [%0], [%1], 16;" :: "r"(saddr), "l"(gaddr));
}
#define CP_COMMIT() asm volatile("cp.async.commit_group;" ::: "memory")
#define CP_WAIT(n)  asm volatile("cp.async.wait_group %0;" :: "n"(n) : "memory")
#define LDMX4(d0,d1,d2,d3,addr) \
    asm volatile("ldmatrix.sync.aligned.m8n8.x4.shared.b16 {%0,%1,%2,%3}, [%4];" \
                 : "=r"(d0), "=r"(d1), "=r"(d2), "=r"(d3) : "r"(addr))
#define PACK_BF2(dst, flo, fhi) \
    asm("cvt.rn.bf16x2.f32 %0, %1, %2;" : "=r"(dst) : "f"(fhi), "f"(flo))
__device__ __forceinline__ uint32_t smem_u32(const void* p) {
    uint32_t a;
    asm("{ .reg .u64 t; cvta.to.shared.u64 t, %1; cvt.u32.u64 %0, t; }" : "=r"(a) : "l"(p));
    return a;
}

__global__ void rope_table_kernel() {
    int idx = blockIdx.x * blockDim.x + threadIdx.x;
    if (idx >= SEQ * 64) return;
    int s = idx >> 6, i = idx & 63;
    double invf = pow(10000.0, -(double)i / 64.0);
    double ang = (double)s * invf;
    g_cos[idx] = (float)cos(ang);
    g_sin[idx] = (float)sin(ang);
}

__global__ void convert_x(const float* __restrict__ src) {
    long idx = (long)blockIdx.x * blockDim.x + threadIdx.x;
    if (idx >= (long)MTOT * (HIDDEN / 4)) return;
    float4 x = ((const float4*)src)[idx];
    __nv_bfloat16 hv[4] = {__float2bfloat16(x.x), __float2bfloat16(x.y),
                           __float2bfloat16(x.z), __float2bfloat16(x.w)};
    __nv_bfloat16 lv[4] = {__float2bfloat16(x.x - __bfloat162float(hv[0])),
                           __float2bfloat16(x.y - __bfloat162float(hv[1])),
                           __float2bfloat16(x.z - __bfloat162float(hv[2])),
                           __float2bfloat16(x.w - __bfloat162float(hv[3]))};
    ((uint2*)g_Ah)[idx] = *(uint2*)hv;
    ((uint2*)g_Al)[idx] = *(uint2*)lv;
}

__global__ void convert_w4(const float* __restrict__ w0, const float* __restrict__ w1,
                           const float* __restrict__ w2, const float* __restrict__ w3) {
    long idx = (long)blockIdx.x * blockDim.x + threadIdx.x;
    const long per = (long)HIDDEN * (HIDDEN / 4);
    if (idx >= 4 * per) return;
    int which = (int)(idx / per);
    long li = idx - (long)which * per;
    const float* src = (which == 0) ? w0 : (which == 1) ? w1 : (which == 2) ? w2 : w3;
    float4 x = ((const float4*)src)[li];
    __nv_bfloat16 hv[4] = {__float2bfloat16(x.x), __float2bfloat16(x.y),
                           __float2bfloat16(x.z), __float2bfloat16(x.w)};
    __nv_bfloat16 lv[4] = {__float2bfloat16(x.x - __bfloat162float(hv[0])),
                           __float2bfloat16(x.y - __bfloat162float(hv[1])),
                           __float2bfloat16(x.z - __bfloat162float(hv[2])),
                           __float2bfloat16(x.w - __bfloat162float(hv[3]))};
    ((uint2*)g_Wh[which])[li] = *(uint2*)hv;
    ((uint2*)g_Wl[which])[li] = *(uint2*)lv;
}

// ------------- GEMM: D = Ah*Wh^T + Ah*Wl^T + Al*Wh^T ---------------------------
// 128x128 tile, 8 warps (2x4), BK=32 true-K, 4 tiles/stage, double buffered.
#define TS    80                      // 64B row + 16B pad
#define TSZ   (128*TS)                // 10240 per tile
#define G_SMEM_BYTES (8*TSZ)          // 81920 (Osm 67584 aliases)

__global__ __launch_bounds__(256)
void gemm3(const __nv_bfloat16* __restrict__ Ah, const __nv_bfloat16* __restrict__ Al,
           const __nv_bfloat16* __restrict__ Wh0, const __nv_bfloat16* __restrict__ Wl0,
           float* __restrict__ Dout, int fused)
{
    extern __shared__ char smem[];
    uint32_t sb = smem_u32(smem);
    int tid = threadIdx.x, wid = tid >> 5, lane = tid & 31;
    int warpm = wid >> 2, warpn = wid & 3;
    int lrw = lane >> 2, lk = lane & 3;

    int n0, mode;
    const __nv_bfloat16 *Wh, *Wl;
    if (fused) {
        int which = blockIdx.x >> 4;
        n0 = (blockIdx.x & 15) * 128;
        Wh = Wh0 + (size_t)which * HIDDEN * HIDDEN;
        Wl = Wl0 + (size_t)which * HIDDEN * HIDDEN;
        mode = which;
    } else { n0 = blockIdx.x * 128; Wh = Wh0; Wl = Wl0; mode = 3; }
    int m0 = blockIdx.y * 128;

    float acc[4][4][4];
    #pragma unroll
    for (int i = 0; i < 4; i++)
        #pragma unroll
        for (int j = 0; j < 4; j++)
            #pragma unroll
            for (int r = 0; r < 4; r++) acc[i][j][r] = 0.f;

    // stage loader: 4 tiles (Ah,Al,Wh,Wl) of 128 rows x 64B; 8 chunks/thread
    int ld_r = tid >> 1, ld_c = (tid & 1) * 32;
    const char* g0[4] = {
        (const char*)(Ah + (size_t)(m0 + ld_r) * HIDDEN),
        (const char*)(Al + (size_t)(m0 + ld_r) * HIDDEN),
        (const char*)(Wh + (size_t)(n0 + ld_r) * HIDDEN),
        (const char*)(Wl + (size_t)(n0 + ld_r) * HIDDEN) };
    auto issue_stage = [&](int kelem, int buf) {
        #pragma unroll
        for (int t = 0; t < 4; t++) {
            uint32_t s = sb + (buf * 4 + t) * TSZ + ld_r * TS + ld_c;
            const char* g = g0[t] + (size_t)kelem * 2 + ld_c;
            cp_async16(s, g);
            cp_async16(s + 16, g + 16);
        }
        CP_COMMIT();
    };

    uint32_t aOff = (uint32_t)((warpm * 64 + (lane & 15)) * TS + ((lane >> 4) << 4));
    uint32_t bOff = (uint32_t)(((lane & 7) + ((lane >> 4) << 3)) * TS + (((lane >> 3) & 1) << 4));

    issue_stage(0, 0);
    for (int st = 0; st < NSTAGE; st++) {
        if (st + 1 < NSTAGE) { issue_stage((st + 1) * BK, (st + 1) & 1); CP_WAIT(1); }
        else                 { CP_WAIT(0); }
        __syncthreads();

        uint32_t base = sb + (st & 1) * 4 * TSZ;
        #pragma unroll
        for (int s = 0; s < 2; s++) {                  // two k16 steps
            uint32_t ah[4][4], al[4][4];
            #pragma unroll
            for (int i = 0; i < 4; i++) {
                LDMX4(ah[i][0], ah[i][1], ah[i][2], ah[i][3],
                      base + aOff + i * 16 * TS + s * 32);
                LDMX4(al[i][0], al[i][1], al[i][2], al[i][3],
                      base + TSZ + aOff + i * 16 * TS + s * 32);
            }
            #pragma unroll
            for (int p = 0; p < 2; p++) {              // 16 n-cols per group
                uint32_t nb = bOff + (warpn * 32 + p * 16) * TS + s * 32;
                uint32_t h0, h1, h2, h3, l0, l1, l2, l3;
                LDMX4(h0, h1, h2, h3, base + 2 * TSZ + nb);
                LDMX4(l0, l1, l2, l3, base + 3 * TSZ + nb);
                uint32_t bh0[2] = {h0, h1}, bh1[2] = {h2, h3};
                uint32_t bl0[2] = {l0, l1}, bl1[2] = {l2, l3};
                #pragma unroll
                for (int i = 0; i < 4; i++) {
                    mma16816(acc[i][2*p],   ah[i], bh0);
                    mma16816(acc[i][2*p+1], ah[i], bh1);
                    mma16816(acc[i][2*p],   ah[i], bl0);
                    mma16816(acc[i][2*p+1], ah[i], bl1);
                    mma16816(acc[i][2*p],   al[i], bh0);
                    mma16816(acc[i][2*p+1], al[i], bh1);
                }
            }
        }
        __syncthreads();
    }

    // ---- epilogue: regs -> Osm, then mode-specific writes ----
    float* Osm = (float*)smem;
    #pragma unroll
    for (int i = 0; i < 4; i++) {
        int r0 = warpm * 64 + i * 16 + lrw;
        #pragma unroll
        for (int j = 0; j < 4; j++) {
            int c0 = warpn * 32 + j * 8 + lk * 2;
            Osm[r0 * 132 + c0]           = acc[i][j][0];
            Osm[r0 * 132 + c0 + 1]       = acc[i][j][1];
            Osm[(r0 + 8) * 132 + c0]     = acc[i][j][2];
            Osm[(r0 + 8) * 132 + c0 + 1] = acc[i][j][3];
        }
    }
    __syncthreads();

    if (mode == 3) {
        #pragma unroll
        for (int it = 0; it < 16; it++) {
            int f = it * 256 + tid;
            int r = f >> 5, c4 = (f & 31) << 2;
            float4 v = *(float4*)&Osm[r * 132 + c4];
            *(float4*)&Dout[(size_t)(m0 + r) * HIDDEN + n0 + c4] = v;
        }
    } else if (mode <= 1) {
        int h = (n0 >> 7) & 15;
        const float scale = (mode == 0) ? 0.08838834764831845f : 1.0f;
        __nv_bfloat16* dst = (mode == 0) ? g_qp : g_kp;
        #pragma unroll
        for (int it = 0; it < 32; it++) {
            int f = it * 256 + tid;
            int r = f >> 6, i = f & 63;
            int m = m0 + r;
            int b = m >> 11, s = m & (SEQ - 1);
            float x1 = Osm[r * 132 + i], x2 = Osm[r * 132 + i + 64];
            float c = g_cos[s * 64 + i], sn = g_sin[s * 64 + i];
            float o1 = (x1 * c - x2 * sn) * scale;
            float o2 = (x2 * c + x1 * sn) * scale;
            __nv_bfloat16 h1 = __float2bfloat16(o1), h2 = __float2bfloat16(o2);
            __nv_bfloat16 l1 = __float2bfloat16(o1 - __bfloat162float(h1));
            __nv_bfloat16 l2 = __float2bfloat16(o2 - __bfloat162float(h2));
            size_t base = ((size_t)(b * HEADS + h) * SEQ + s) * 256;
            dst[base + i] = h1; dst[base + i + 64] = h2;
            dst[base + 128 + i] = l1; dst[base + 128 + i + 64] = l2;
        }
    } else {
        int h = (n0 >> 7) & 15;
        #pragma unroll
        for (int it = 0; it < 64; it++) {
            int f = it * 256 + tid;
            int mloc = f & 127, d = (f >> 7) & 127;
            float val = Osm[mloc * 132 + d];
            int m = m0 + mloc;
            int b = m >> 11, s = m & (SEQ - 1);
            __nv_bfloat16 hv = __float2bfloat16(val);
            __nv_bfloat16 lv = __float2bfloat16(val - __bfloat162float(hv));
            size_t o = ((size_t)((b * HEADS + h) * HD + d)) * SEQ + s;
            g_vh[o] = hv; g_vl[o] = lv;
        }
    }
}

// ------------- tensor-core flash attention -------------------------------------
#define AQ_STR 528
#define AK_STR 528
#define AV_STR 272
#define AOFF_K (128*AQ_STR)
#define AK_SZ  (64*AK_STR)
#define AOFF_V (AOFF_K + 2*AK_SZ)
#define AV_SZ  (128*AV_STR)
#define ATTN_SMEM (AOFF_V + 2*AV_SZ)
#define NEGB   -1e30f

__global__ __launch_bounds__(256, 1)
void attn_kernel()
{
    extern __shared__ char sm[];
    uint32_t sb = smem_u32(sm);
    int tid = threadIdx.x, wid = tid >> 5, lane = tid & 31;
    int lrw = lane >> 2, lk = lane & 3;
    int qt = 15 - (blockIdx.x >> 5);     // heavy-first linear schedule
    int bh = blockIdx.x & 31;

    {
        int r = tid >> 1, c0 = (tid & 1) * 256;
        uint32_t s = sb + r * AQ_STR + c0;
        const char* g = (const char*)g_qp + ((size_t)bh * SEQ + (size_t)qt * 128 + r) * 512 + c0;
        #pragma unroll
        for (int j = 0; j < 16; j++) cp_async16(s + j * 16, g + j * 16);
        CP_COMMIT();
    }
    int kr = tid >> 2, kc = (tid & 3) * 128;
    int vr = tid >> 1, vh = tid & 1;
    auto issue_kv = [&](int kt, int buf) {
        uint32_t s = sb + AOFF_K + buf * AK_SZ + kr * AK_STR + kc;
        const char* g = (const char*)g_kp + ((size_t)bh * SEQ + (size_t)kt * 64 + kr) * 512 + kc;
        #pragma unroll
        for (int j = 0; j < 8; j++) cp_async16(s + j * 16, g + j * 16);
        uint32_t sv = sb + AOFF_V + buf * AV_SZ + vr * AV_STR + vh * 128;
        const __nv_bfloat16* vg = (vh ? g_vl : g_vh) + ((size_t)bh * HD + vr) * SEQ + (size_t)kt * 64;
        #pragma unroll
        for (int j = 0; j < 8; j++) cp_async16(sv + j * 16, (const char*)vg + j * 16);
        CP_COMMIT();
    };

    float accO[16][4];
    #pragma unroll
    for (int nt = 0; nt < 16; nt++)
        #pragma unroll
        for (int r = 0; r < 4; r++) accO[nt][r] = 0.f;
    float mA = NEGB, mB = NEGB, lA = 0.f, lB = 0.f;

    uint32_t qfb = sb + (wid * 16 + (lane & 15)) * AQ_STR + ((lane >> 4) << 4);
    uint32_t kfo = (uint32_t)(((lane & 7) + ((lane >> 4) << 3)) * AK_STR + (((lane >> 3) & 1) << 4));
    uint32_t vfo = (uint32_t)(((lane & 7) + ((lane >> 4) << 3)) * AV_STR + (((lane >> 3) & 1) << 4));
    int rgA = qt * 128 + wid * 16 + lrw;
    int nkt = 2 * qt + 2;

    issue_kv(0, 0);
    for (int kt = 0; kt < nkt; kt++) {
        if (kt + 1 < nkt) { issue_kv(kt + 1, (kt + 1) & 1); CP_WAIT(1); }
        else              { CP_WAIT(0); }
        __syncthreads();

        if (kt * 64 <= qt * 128 + wid * 16 + 15) {
            float sacc[8][4];
            #pragma unroll
            for (int nt = 0; nt < 8; nt++)
                #pragma unroll
                for (int r = 0; r < 4; r++) sacc[nt][r] = 0.f;

            uint32_t kbuf = sb + AOFF_K + (kt & 1) * AK_SZ + kfo;
            #pragma unroll
            for (int pass = 0; pass < 3; pass++) {
                uint32_t qo = qfb + (pass == 2 ? 256u : 0u);
                uint32_t ko = kbuf + (pass == 1 ? 256u : 0u);
                #pragma unroll
                for (int ks = 0; ks < 8; ks++) {
                    uint32_t af[4];
                    LDMX4(af[0], af[1], af[2], af[3], qo + ks * 32);
                    #pragma unroll
                    for (int np = 0; np < 4; np++) {
                        uint32_t b0, b1, b2, b3;
                        LDMX4(b0, b1, b2, b3, ko + np * 16 * AK_STR + ks * 32);
                        uint32_t bf0[2] = {b0, b1}, bf1[2] = {b2, b3};
                        mma16816(sacc[2*np],   af, bf0);
                        mma16816(sacc[2*np+1], af, bf1);
                    }
                }
            }
            if (kt * 64 + 63 > qt * 128 + wid * 16) {
                #pragma unroll
                for (int nt = 0; nt < 8; nt++) {
                    int cg = kt * 64 + nt * 8 + 2 * lk;
                    if (cg     > rgA)     sacc[nt][0] = NEGB;
                    if (cg + 1 > rgA)     sacc[nt][1] = NEGB;
                    if (cg     > rgA + 8) sacc[nt][2] = NEGB;
                    if (cg + 1 > rgA + 8) sacc[nt][3] = NEGB;
                }
            }
            float nmA = mA, nmB = mB;
            #pragma unroll
            for (int nt = 0; nt < 8; nt++) {
                nmA = fmaxf(nmA, fmaxf(sacc[nt][0], sacc[nt][1]));
                nmB = fmaxf(nmB, fmaxf(sacc[nt][2], sacc[nt][3]));
            }
            nmA = fmaxf(nmA, __shfl_xor_sync(~0u, nmA, 1));
            nmA = fmaxf(nmA, __shfl_xor_sync(~0u, nmA, 2));
            nmB = fmaxf(nmB, __shfl_xor_sync(~0u, nmB, 1));
            nmB = fmaxf(nmB, __shfl_xor_sync(~0u, nmB, 2));
            float coA = __expf(mA - nmA), coB = __expf(mB - nmB);
            mA = nmA; mB = nmB;
            float sumA = 0.f, sumB = 0.f;
            #pragma unroll
            for (int nt = 0; nt < 8; nt++) {
                sacc[nt][0] = __expf(sacc[nt][0] - nmA);
                sacc[nt][1] = __expf(sacc[nt][1] - nmA);
                sacc[nt][2] = __expf(sacc[nt][2] - nmB);
                sacc[nt][3] = __expf(sacc[nt][3] - nmB);
                sumA += sacc[nt][0] + sacc[nt][1];
                sumB += sacc[nt][2] + sacc[nt][3];
            }
            sumA += __shfl_xor_sync(~0u, sumA, 1);
            sumA += __shfl_xor_sync(~0u, sumA, 2);
            sumB += __shfl_xor_sync(~0u, sumB, 1);
            sumB += __shfl_xor_sync(~0u, sumB, 2);
            lA = lA * coA + sumA;
            lB = lB * coB + sumB;
            #pragma unroll
            for (int nt = 0; nt < 16; nt++) {
                accO[nt][0] *= coA; accO[nt][1] *= coA;
                accO[nt][2] *= coB; accO[nt][3] *= coB;
            }
            uint32_t phi[4][4], plo[4][4];
            #pragma unroll
            for (int s = 0; s < 4; s++) {
                #pragma unroll
                for (int half = 0; half < 2; half++) {
                    int nt = 2 * s + half;
                    float p0 = sacc[nt][0], p1 = sacc[nt][1];
                    float p2 = sacc[nt][2], p3 = sacc[nt][3];
                    PACK_BF2(phi[s][2*half],   p0, p1);
                    PACK_BF2(phi[s][2*half+1], p2, p3);
                    float r0 = p0 - __bfloat162float(__float2bfloat16(p0));
                    float r1 = p1 - __bfloat162float(__float2bfloat16(p1));
                    float r2 = p2 - __bfloat162float(__float2bfloat16(p2));
                    float r3 = p3 - __bfloat162float(__float2bfloat16(p3));
                    PACK_BF2(plo[s][2*half],   r0, r1);
                    PACK_BF2(plo[s][2*half+1], r2, r3);
                }
            }
            uint32_t vbuf = sb + AOFF_V + (kt & 1) * AV_SZ + vfo;
            #pragma unroll
            for (int pass = 0; pass < 3; pass++) {
                uint32_t voff = (pass == 1) ? 128u : 0u;
                #pragma unroll
                for (int ks = 0; ks < 4; ks++) {
                    const uint32_t* P = (pass == 2) ? plo[ks] : phi[ks];
                    #pragma unroll
                    for (int nt16 = 0; nt16 < 8; nt16++) {
                        uint32_t b0, b1, b2, b3;
                        LDMX4(b0, b1, b2, b3, vbuf + nt16 * 16 * AV_STR + ks * 32 + voff);
                        uint32_t bf0[2] = {b0, b1}, bf1[2] = {b2, b3};
                        mma16816(accO[2*nt16],   P, bf0);
                        mma16816(accO[2*nt16+1], P, bf1);
                    }
                }
            }
        }
        __syncthreads();
    }

    float iA = 1.f / lA, iB = 1.f / lB;
    float* Osm = (float*)sm;
    int r0 = wid * 16 + lrw;
    #pragma unroll
    for (int nt = 0; nt < 16; nt++) {
        int c = nt * 8 + 2 * lk;
        *(float2*)&Osm[r0 * 132 + c]       = make_float2(accO[nt][0] * iA, accO[nt][1] * iA);
        *(float2*)&Osm[(r0 + 8) * 132 + c] = make_float2(accO[nt][2] * iB, accO[nt][3] * iB);
    }
    __syncthreads();
    int bb = bh >> 4, h = bh & 15;
    #pragma unroll
    for (int it = 0; it < 32; it++) {
        int f = it * 256 + tid;
        int r = f >> 6, d2 = (f & 63) * 2;
        float v0 = Osm[r * 132 + d2], v1 = Osm[r * 132 + d2 + 1];
        __nv_bfloat16 hb[2] = {__float2bfloat16(v0), __float2bfloat16(v1)};
        __nv_bfloat16 lb[2] = {__float2bfloat16(v0 - __bfloat162float(hb[0])),
                               __float2bfloat16(v1 - __bfloat162float(hb[1]))};
        size_t row = (size_t)bb * SEQ + (size_t)qt * 128 + r;
        size_t off = row * HIDDEN + h * 128 + d2;
        *(uint32_t*)(g_Ch + off) = *(uint32_t*)hb;
        *(uint32_t*)(g_Cl + off) = *(uint32_t*)lb;
    }
}

// ------------- launcher ---------------------------------------------------------
extern "C" void kernel_launch(void* const* d_in, const int* in_sizes, int n_in,
                              void* d_out, int out_size)
{
    (void)in_sizes; (void)n_in; (void)out_size;
    const float* X  = (const float*)d_in[0];
    const float* wq = (const float*)d_in[1];
    const float* wk = (const float*)d_in[2];
    const float* wv = (const float*)d_in[3];
    const float* wo = (const float*)d_in[4];
    float* out = (float*)d_out;

    __nv_bfloat16 *ah, *al, *wh, *wl, *ch, *cl;
    cudaGetSymbolAddress((void**)&ah, g_Ah);
    cudaGetSymbolAddress((void**)&al, g_Al);
    cudaGetSymbolAddress((void**)&wh, g_Wh);
    cudaGetSymbolAddress((void**)&wl, g_Wl);
    cudaGetSymbolAddress((void**)&ch, g_Ch);
    cudaGetSymbolAddress((void**)&cl, g_Cl);

    cudaFuncSetAttribute(gemm3, cudaFuncAttributeMaxDynamicSharedMemorySize, G_SMEM_BYTES);
    cudaFuncSetAttribute(attn_kernel, cudaFuncAttributeMaxDynamicSharedMemorySize, ATTN_SMEM);

    rope_table_kernel<<<(SEQ * 64 + 255) / 256, 256>>>();

    convert_x<<<(MTOT * HIDDEN / 4 + 255) / 256, 256>>>(X);
    convert_w4<<<(4 * HIDDEN * (HIDDEN / 4) + 255) / 256, 256>>>(wq, wk, wv, wo);

    // fused QKV projections + RoPE/scale epilogues
    gemm3<<<dim3(48, 32), 256, G_SMEM_BYTES>>>(ah, al, wh, wl, out, 1);

    attn_kernel<<<512, 256, ATTN_SMEM>>>();

    // output projection (weights index 3)
    gemm3<<<dim3(16, 32), 256, G_SMEM_BYTES>>>(
        ch, cl,
        wh + (size_t)3 * HIDDEN * HIDDEN, wl + (size_t)3 * HIDDEN * HIDDEN,
        out, 0);
}